// round 12
// baseline (speedup 1.0000x reference)
#include <cuda_runtime.h>
#include <cuda_fp16.h>
#include <cstdint>

// SoftPixelCNN R12: tensor-core reformulation.
// Per vertex: D[9x64] = (W/32)[9x32] . F[32x64] as one warp-level GEMM
// (M=16 padded, N=64, K=32) via 16x mma.sync.m16n8k16.f32.f16.f16.f32.
// Phase 1: lane k computes the 9 offset weights for neighbor k, scales by
// 1/K, converts to fp16, stores W^T row k (16 cols, o>=9 zero) in SMEM.
// Phase 2: warp gathers the 32 neighbor feature rows (fp16, 128B each) into
// SMEM (LDG.128 + STS.128, 4 rows per warp-op). ldmatrix.x4.trans builds
// A-frags from W^T and B-frags from F; mma accumulates in fp32; epilogue is
// pure float2 stores from c-frags (mean already folded into W).

typedef unsigned u32;

#define MAXV 50176
__device__ __align__(16) uint4 g_hfeats[MAXV * 8];   // V x 64 fp16 (128 B rows)

__device__ __forceinline__ u32 pack_h2(float a, float b) {
    const __half2 h = __floats2half2_rn(a, b);
    return *(const u32*)&h;
}

__global__ __launch_bounds__(256)
void cvt_kernel(const float* __restrict__ feats, int n8)  // n8 = V*8
{
    const int i = blockIdx.x * blockDim.x + threadIdx.x;
    if (i >= n8) return;
    const float4 a = ((const float4*)feats)[2 * i];
    const float4 b = ((const float4*)feats)[2 * i + 1];
    uint4 r;
    r.x = pack_h2(a.x, a.y);
    r.y = pack_h2(a.z, a.w);
    r.z = pack_h2(b.x, b.y);
    r.w = pack_h2(b.z, b.w);
    g_hfeats[i] = r;
}

__device__ __forceinline__ u32 smem_u32(const void* p) {
    return (u32)__cvta_generic_to_shared(p);
}

#define LDSM_X4_TRANS(x0, x1, x2, x3, addr)                                   \
    asm volatile("ldmatrix.sync.aligned.m8n8.x4.trans.shared.b16 "            \
                 "{%0,%1,%2,%3}, [%4];"                                        \
                 : "=r"(x0), "=r"(x1), "=r"(x2), "=r"(x3) : "r"(addr))

#define MMA16816(c, a0, a1, a2, a3, b0, b1)                                   \
    asm volatile("mma.sync.aligned.m16n8k16.row.col.f32.f16.f16.f32 "         \
                 "{%0,%1,%2,%3}, {%4,%5,%6,%7}, {%8,%9}, {%0,%1,%2,%3};"       \
                 : "+f"((c)[0]), "+f"((c)[1]), "+f"((c)[2]), "+f"((c)[3])      \
                 : "r"(a0), "r"(a1), "r"(a2), "r"(a3), "r"(b0), "r"(b1))

__global__ __launch_bounds__(128, 8)
void spcnn_kernel(const float* __restrict__ coords,   // (V,4)
                  const int*   __restrict__ nbr,      // (V,32)
                  const float* __restrict__ ls,       // (1,)
                  float*       __restrict__ out,      // (V,576)
                  int V)
{
    const int warp = threadIdx.x >> 5;
    const int lane = threadIdx.x & 31;
    const int v    = blockIdx.x * 4 + warp;

    struct WS {
        __half wt[32][16];   // 1024 B: W^T, row k = [w0..w8, 0 x7] (scaled 1/K)
        __half f [32][64];   // 4096 B: gathered neighbor feature rows
        int    ib[32];       // 128 B : neighbor indices
    };
    __shared__ __align__(16) WS ws[4];
    WS& S = ws[warp];

    if (v >= V) return;
    const float g = 10.0f * ls[0];

    // ---------------- Phase 1: lane k -> W^T row k (fp16, mean-folded) ---------
    {
        const int idx = nbr[v * 32 + lane];
        const float4 cv = ((const float4*)coords)[v];
        const float4 cn = ((const float4*)coords)[idx];
        const float dx = cv.x - cn.x;
        const float dy = cv.y - cn.y;
        const float dz = cv.z - cn.z;
        const float dw = cv.w - cn.w;
        const float base = dx*dx + dy*dy + dz*dz + dw*dw;
        const float b1 = base + 1.0f;

        // OFFSETS (verified R1): o0=0 o1=-y o2=-x o3=-z o4=-w o5=+w o6=+z o7=+x o8=+y
        const float s = 0.03125f;   // 1/K folded into W
        const float w0 = s * __expf(-g * base);
        const float w1 = s * __expf(-g * (b1 - 2.0f * dy));
        const float w2 = s * __expf(-g * (b1 - 2.0f * dx));
        const float w3 = s * __expf(-g * (b1 - 2.0f * dz));
        const float w4 = s * __expf(-g * (b1 - 2.0f * dw));
        const float w5 = s * __expf(-g * (b1 + 2.0f * dw));
        const float w6 = s * __expf(-g * (b1 + 2.0f * dz));
        const float w7 = s * __expf(-g * (b1 + 2.0f * dx));
        const float w8 = s * __expf(-g * (b1 + 2.0f * dy));

        uint4 lo, hi;
        lo.x = pack_h2(w0, w1);
        lo.y = pack_h2(w2, w3);
        lo.z = pack_h2(w4, w5);
        lo.w = pack_h2(w6, w7);
        hi.x = pack_h2(w8, 0.0f);
        hi.y = 0u; hi.z = 0u; hi.w = 0u;
        *(uint4*)&S.wt[lane][0] = lo;
        *(uint4*)&S.wt[lane][8] = hi;
        S.ib[lane] = idx;
    }
    __syncwarp();

    // ---------------- Phase 2a: gather 32 feature rows into SMEM ---------------
    {
        const int r0 = lane >> 3;           // row within group of 4
        const int bo = (lane & 7) * 16;     // byte offset within 128B row
        const char* hf = (const char*)g_hfeats;
        char* fs = (char*)S.f;
        #pragma unroll
        for (int it = 0; it < 8; ++it) {
            const int r = it * 4 + r0;
            const int n = S.ib[r];
            const uint4 d = *(const uint4*)(hf + (size_t)n * 128 + bo);
            *(uint4*)(fs + r * 128 + bo) = d;
        }
    }
    __syncwarp();

    // ---------------- Phase 2b: ldmatrix + mma ----------------------------------
    // A (16x32) from W^T via x4.trans:  blocks (m0-7,k0-7)(m8-15,k0-7)(m0-7,k8-15)(m8-15,k8-15)
    // B (32x64) from F via x4.trans:    blocks (k0-7,nt)(k8-15,nt)(k0-7,nt+1)(k8-15,nt+1)
    const int q  = lane >> 3;
    const int rr = lane & 7;
    const u32 wtb = smem_u32(S.wt);
    const u32 fb  = smem_u32(S.f);
    const u32 addrA = wtb + (u32)(((q & 2) ? 8 + rr : rr) * 32 + (q & 1) * 16);
    const u32 addrB = fb  + (u32)(((q & 1) ? 8 + rr : rr) * 128 + (q >> 1) * 16);

    float c[8][4];
    #pragma unroll
    for (int t = 0; t < 8; ++t)
        #pragma unroll
        for (int j = 0; j < 4; ++j) c[t][j] = 0.0f;

    #pragma unroll
    for (int kt = 0; kt < 2; ++kt) {
        u32 a0, a1, a2, a3;
        LDSM_X4_TRANS(a0, a1, a2, a3, addrA + kt * 512);   // +16 W^T rows
        #pragma unroll
        for (int tp = 0; tp < 4; ++tp) {
            u32 b0, b1, b2, b3;
            LDSM_X4_TRANS(b0, b1, b2, b3, addrB + kt * 2048 + tp * 32);
            MMA16816(c[2 * tp],     a0, a1, a2, a3, b0, b1);
            MMA16816(c[2 * tp + 1], a0, a1, a2, a3, b2, b3);
        }
    }

    // ---------------- Epilogue: store c-frags (mean already applied) -----------
    // c[t][0,1] = D[gg][t*8 + tg*2 .. +1]  (offsets 0-7)
    // c[t][2,3] = D[gg+8][...]             (offset 8 lives in gg==0, lanes 0-3)
    const int gg = lane >> 2;
    const int tg = lane & 3;
    float* orow = out + (size_t)v * 576;

    #pragma unroll
    for (int t = 0; t < 8; ++t)
        *(float2*)(orow + gg * 64 + t * 8 + tg * 2) = make_float2(c[t][0], c[t][1]);

    if (gg == 0) {
        #pragma unroll
        for (int t = 0; t < 8; ++t)
            *(float2*)(orow + 8 * 64 + t * 8 + tg * 2) = make_float2(c[t][2], c[t][3]);
    }
}

extern "C" void kernel_launch(void* const* d_in, const int* in_sizes, int n_in,
                              void* d_out, int out_size)
{
    const float* coords = (const float*)d_in[0];
    const float* feats  = (const float*)d_in[1];
    const int*   nbr    = (const int*)  d_in[3];
    const float* ls     = (const float*)d_in[4];
    float* out = (float*)d_out;

    const int V = in_sizes[0] / 4;

    // pre-pass: fp32 -> fp16 feature table
    const int n8 = V * 8;
    cvt_kernel<<<(n8 + 255) / 256, 256>>>(feats, n8);

    const int blocks = (V + 3) / 4;   // one vertex per warp, 4 warps/block
    spcnn_kernel<<<blocks, 128>>>(coords, nbr, ls, out, V);
}

// round 13
// speedup vs baseline: 1.7428x; 1.7428x over previous
#include <cuda_runtime.h>
#include <cuda_fp16.h>
#include <cstdint>

// SoftPixelCNN R13: R12 tensor-core kernel + conflict-free SMEM swizzles.
// R12 was correct but ldmatrix.trans on unswizzled SMEM was 8-way bank
// conflicted (L1 84% @ issue 11%). Fixes:
//  - F tile: XOR swizzle, physical 16B-chunk = chunk ^ (row & 7); gather STS
//    writes through the same swizzle; ldmatrix B now 4 wf per x4 op.
//  - W^T tile: rows padded 32B -> 48B (stride of 12 banks) making both the
//    phase-1 STS and ldmatrix A conflict-free.
//  - Gather: 8 indices preloaded, LDGs batched 4-wide (MLP=4).

typedef unsigned u32;

#define MAXV 50176
__device__ __align__(16) uint4 g_hfeats[MAXV * 8];   // V x 64 fp16 (128 B rows)

__device__ __forceinline__ u32 pack_h2(float a, float b) {
    const __half2 h = __floats2half2_rn(a, b);
    return *(const u32*)&h;
}

__global__ __launch_bounds__(256)
void cvt_kernel(const float* __restrict__ feats, int n8)  // n8 = V*8
{
    const int i = blockIdx.x * blockDim.x + threadIdx.x;
    if (i >= n8) return;
    const float4 a = ((const float4*)feats)[2 * i];
    const float4 b = ((const float4*)feats)[2 * i + 1];
    uint4 r;
    r.x = pack_h2(a.x, a.y);
    r.y = pack_h2(a.z, a.w);
    r.z = pack_h2(b.x, b.y);
    r.w = pack_h2(b.z, b.w);
    g_hfeats[i] = r;
}

__device__ __forceinline__ u32 smem_u32(const void* p) {
    return (u32)__cvta_generic_to_shared(p);
}

#define LDSM_X4_TRANS(x0, x1, x2, x3, addr)                                   \
    asm volatile("ldmatrix.sync.aligned.m8n8.x4.trans.shared.b16 "            \
                 "{%0,%1,%2,%3}, [%4];"                                        \
                 : "=r"(x0), "=r"(x1), "=r"(x2), "=r"(x3) : "r"(addr))

#define MMA16816(c, a0, a1, a2, a3, b0, b1)                                   \
    asm volatile("mma.sync.aligned.m16n8k16.row.col.f32.f16.f16.f32 "         \
                 "{%0,%1,%2,%3}, {%4,%5,%6,%7}, {%8,%9}, {%0,%1,%2,%3};"       \
                 : "+f"((c)[0]), "+f"((c)[1]), "+f"((c)[2]), "+f"((c)[3])      \
                 : "r"(a0), "r"(a1), "r"(a2), "r"(a3), "r"(b0), "r"(b1))

__global__ __launch_bounds__(128, 8)
void spcnn_kernel(const float* __restrict__ coords,   // (V,4)
                  const int*   __restrict__ nbr,      // (V,32)
                  const float* __restrict__ ls,       // (1,)
                  float*       __restrict__ out,      // (V,576)
                  int V)
{
    const int warp = threadIdx.x >> 5;
    const int lane = threadIdx.x & 31;
    const int v    = blockIdx.x * 4 + warp;

    struct WS {
        __half wt[32][24];   // 1536 B: W^T rows padded to 48B (conflict-free)
        __half f [32][64];   // 4096 B: gathered rows, chunk-XOR swizzled
        int    ib[32];       // 128 B : neighbor indices
    };
    __shared__ __align__(16) WS ws[4];
    WS& S = ws[warp];

    if (v >= V) return;
    const float g = 10.0f * ls[0];

    // ---------------- Phase 1: lane k -> W^T row k (fp16, mean-folded) ---------
    {
        const int idx = nbr[v * 32 + lane];
        const float4 cv = ((const float4*)coords)[v];
        const float4 cn = ((const float4*)coords)[idx];
        const float dx = cv.x - cn.x;
        const float dy = cv.y - cn.y;
        const float dz = cv.z - cn.z;
        const float dw = cv.w - cn.w;
        const float base = dx*dx + dy*dy + dz*dz + dw*dw;
        const float b1 = base + 1.0f;

        // OFFSETS (verified R1): o0=0 o1=-y o2=-x o3=-z o4=-w o5=+w o6=+z o7=+x o8=+y
        const float s = 0.03125f;   // 1/K folded into W
        const float w0 = s * __expf(-g * base);
        const float w1 = s * __expf(-g * (b1 - 2.0f * dy));
        const float w2 = s * __expf(-g * (b1 - 2.0f * dx));
        const float w3 = s * __expf(-g * (b1 - 2.0f * dz));
        const float w4 = s * __expf(-g * (b1 - 2.0f * dw));
        const float w5 = s * __expf(-g * (b1 + 2.0f * dw));
        const float w6 = s * __expf(-g * (b1 + 2.0f * dz));
        const float w7 = s * __expf(-g * (b1 + 2.0f * dx));
        const float w8 = s * __expf(-g * (b1 + 2.0f * dy));

        uint4 lo, hi;
        lo.x = pack_h2(w0, w1);
        lo.y = pack_h2(w2, w3);
        lo.z = pack_h2(w4, w5);
        lo.w = pack_h2(w6, w7);
        hi.x = pack_h2(w8, 0.0f);
        hi.y = 0u; hi.z = 0u; hi.w = 0u;
        *(uint4*)&S.wt[lane][0] = lo;    // bytes 0-15  (k-chunk 0)
        *(uint4*)&S.wt[lane][8] = hi;    // bytes 16-31 (k-chunk 1)
        S.ib[lane] = idx;
    }
    __syncwarp();

    // ---------------- Phase 2a: gather 32 rows into swizzled SMEM ---------------
    {
        const int r0 = lane >> 3;           // row-within-4-group
        const int c0 = lane & 7;            // 16B chunk
        const char* hf = (const char*)g_hfeats;
        char* fs = (char*)S.f;

        int nidx[8];
        #pragma unroll
        for (int it = 0; it < 8; ++it) nidx[it] = S.ib[it * 4 + r0];

        #pragma unroll
        for (int h = 0; h < 2; ++h) {
            uint4 d[4];
            #pragma unroll
            for (int u = 0; u < 4; ++u)
                d[u] = *(const uint4*)(hf + (size_t)nidx[h * 4 + u] * 128 + c0 * 16);
            #pragma unroll
            for (int u = 0; u < 4; ++u) {
                const int r = (h * 4 + u) * 4 + r0;
                *(uint4*)(fs + r * 128 + ((c0 ^ (r & 7)) << 4)) = d[u];
            }
        }
    }
    __syncwarp();

    // ---------------- Phase 2b: ldmatrix (swizzle-aware) + mma ------------------
    const int q  = lane >> 3;
    const int rr = lane & 7;
    const u32 wtb = smem_u32(S.wt);
    const u32 fb  = smem_u32(S.f);

    // A: matrix q -> rows ((q&2)?8+rr:rr), k-chunk (q&1); row stride 48B
    const int lrA = ((q & 2) ? 8 : 0) + rr;
    const u32 addrA0 = wtb + (u32)(lrA * 48 + (q & 1) * 16);
    // B: matrix q -> rows ((q&1)?8+rr:rr), chunk base (q>>1); swizzled by rr
    const int lrB = ((q & 1) ? 8 : 0) + rr;
    const int chB = q >> 1;

    float c[8][4];
    #pragma unroll
    for (int t = 0; t < 8; ++t)
        #pragma unroll
        for (int j = 0; j < 4; ++j) c[t][j] = 0.0f;

    #pragma unroll
    for (int kt = 0; kt < 2; ++kt) {
        u32 a0, a1, a2, a3;
        LDSM_X4_TRANS(a0, a1, a2, a3, addrA0 + kt * (16 * 48));
        const u32 rowB = fb + (u32)((lrB + kt * 16) * 128);
        #pragma unroll
        for (int tp = 0; tp < 4; ++tp) {
            const int ch = chB + tp * 2;
            u32 b0, b1, b2, b3;
            LDSM_X4_TRANS(b0, b1, b2, b3, rowB + (u32)(((ch ^ rr) << 4)));
            MMA16816(c[2 * tp],     a0, a1, a2, a3, b0, b1);
            MMA16816(c[2 * tp + 1], a0, a1, a2, a3, b2, b3);
        }
    }

    // ---------------- Epilogue: store c-frags (mean already applied) -----------
    const int gg = lane >> 2;
    const int tg = lane & 3;
    float* orow = out + (size_t)v * 576;

    #pragma unroll
    for (int t = 0; t < 8; ++t)
        *(float2*)(orow + gg * 64 + t * 8 + tg * 2) = make_float2(c[t][0], c[t][1]);

    if (gg == 0) {
        #pragma unroll
        for (int t = 0; t < 8; ++t)
            *(float2*)(orow + 8 * 64 + t * 8 + tg * 2) = make_float2(c[t][2], c[t][3]);
    }
}

extern "C" void kernel_launch(void* const* d_in, const int* in_sizes, int n_in,
                              void* d_out, int out_size)
{
    const float* coords = (const float*)d_in[0];
    const float* feats  = (const float*)d_in[1];
    const int*   nbr    = (const int*)  d_in[3];
    const float* ls     = (const float*)d_in[4];
    float* out = (float*)d_out;

    const int V = in_sizes[0] / 4;

    // pre-pass: fp32 -> fp16 feature table
    const int n8 = V * 8;
    cvt_kernel<<<(n8 + 255) / 256, 256>>>(feats, n8);

    const int blocks = (V + 3) / 4;   // one vertex per warp, 4 warps/block
    spcnn_kernel<<<blocks, 128>>>(coords, nbr, ls, out, V);
}

// round 14
// speedup vs baseline: 1.9954x; 1.1449x over previous
#include <cuda_runtime.h>
#include <cuda_fp16.h>
#include <cstdint>

// SoftPixelCNN R14: R13 tensor-core kernel, with the gather's LDG+STS pair
// replaced by cp.async.cg (global -> swizzled SMEM direct, 16B/lane).
// Removes the 32 STS wavefronts per vertex and the fv register middleman;
// A-fragment ldmatrix runs while the async copies are in flight.
// Swizzles from R13 (verified): F chunk = chunk ^ (row & 7); W^T rows 48B.

typedef unsigned u32;

#define MAXV 50176
__device__ __align__(16) uint4 g_hfeats[MAXV * 8];   // V x 64 fp16 (128 B rows)

__device__ __forceinline__ u32 pack_h2(float a, float b) {
    const __half2 h = __floats2half2_rn(a, b);
    return *(const u32*)&h;
}

__global__ __launch_bounds__(256)
void cvt_kernel(const float* __restrict__ feats, int n8)  // n8 = V*8
{
    const int i = blockIdx.x * blockDim.x + threadIdx.x;
    if (i >= n8) return;
    const float4 a = ((const float4*)feats)[2 * i];
    const float4 b = ((const float4*)feats)[2 * i + 1];
    uint4 r;
    r.x = pack_h2(a.x, a.y);
    r.y = pack_h2(a.z, a.w);
    r.z = pack_h2(b.x, b.y);
    r.w = pack_h2(b.z, b.w);
    g_hfeats[i] = r;
}

__device__ __forceinline__ u32 smem_u32(const void* p) {
    return (u32)__cvta_generic_to_shared(p);
}

#define LDSM_X4_TRANS(x0, x1, x2, x3, addr)                                   \
    asm volatile("ldmatrix.sync.aligned.m8n8.x4.trans.shared.b16 "            \
                 "{%0,%1,%2,%3}, [%4];"                                        \
                 : "=r"(x0), "=r"(x1), "=r"(x2), "=r"(x3) : "r"(addr))

#define MMA16816(c, a0, a1, a2, a3, b0, b1)                                   \
    asm volatile("mma.sync.aligned.m16n8k16.row.col.f32.f16.f16.f32 "         \
                 "{%0,%1,%2,%3}, {%4,%5,%6,%7}, {%8,%9}, {%0,%1,%2,%3};"       \
                 : "+f"((c)[0]), "+f"((c)[1]), "+f"((c)[2]), "+f"((c)[3])      \
                 : "r"(a0), "r"(a1), "r"(a2), "r"(a3), "r"(b0), "r"(b1))

__global__ __launch_bounds__(128, 8)
void spcnn_kernel(const float* __restrict__ coords,   // (V,4)
                  const int*   __restrict__ nbr,      // (V,32)
                  const float* __restrict__ ls,       // (1,)
                  float*       __restrict__ out,      // (V,576)
                  int V)
{
    const int warp = threadIdx.x >> 5;
    const int lane = threadIdx.x & 31;
    const int v    = blockIdx.x * 4 + warp;

    struct WS {
        __half wt[32][24];   // 1536 B: W^T rows padded to 48B (conflict-free)
        __half f [32][64];   // 4096 B: gathered rows, chunk-XOR swizzled
        int    ib[32];       // 128 B : neighbor indices
    };
    __shared__ __align__(16) WS ws[4];
    WS& S = ws[warp];

    if (v >= V) return;
    const float g = 10.0f * ls[0];

    // ---------------- Phase 1: lane k -> W^T row k (fp16, mean-folded) ---------
    {
        const int idx = nbr[v * 32 + lane];
        const float4 cv = ((const float4*)coords)[v];
        const float4 cn = ((const float4*)coords)[idx];
        const float dx = cv.x - cn.x;
        const float dy = cv.y - cn.y;
        const float dz = cv.z - cn.z;
        const float dw = cv.w - cn.w;
        const float base = dx*dx + dy*dy + dz*dz + dw*dw;
        const float b1 = base + 1.0f;

        // OFFSETS (verified R1): o0=0 o1=-y o2=-x o3=-z o4=-w o5=+w o6=+z o7=+x o8=+y
        const float s = 0.03125f;   // 1/K folded into W
        const float w0 = s * __expf(-g * base);
        const float w1 = s * __expf(-g * (b1 - 2.0f * dy));
        const float w2 = s * __expf(-g * (b1 - 2.0f * dx));
        const float w3 = s * __expf(-g * (b1 - 2.0f * dz));
        const float w4 = s * __expf(-g * (b1 - 2.0f * dw));
        const float w5 = s * __expf(-g * (b1 + 2.0f * dw));
        const float w6 = s * __expf(-g * (b1 + 2.0f * dz));
        const float w7 = s * __expf(-g * (b1 + 2.0f * dx));
        const float w8 = s * __expf(-g * (b1 + 2.0f * dy));

        uint4 lo, hi;
        lo.x = pack_h2(w0, w1);
        lo.y = pack_h2(w2, w3);
        lo.z = pack_h2(w4, w5);
        lo.w = pack_h2(w6, w7);
        hi.x = pack_h2(w8, 0.0f);
        hi.y = 0u; hi.z = 0u; hi.w = 0u;
        *(uint4*)&S.wt[lane][0] = lo;    // bytes 0-15  (k-chunk 0)
        *(uint4*)&S.wt[lane][8] = hi;    // bytes 16-31 (k-chunk 1)
        S.ib[lane] = idx;
    }
    __syncwarp();

    // ---------------- Phase 2a: async gather straight into swizzled SMEM --------
    {
        const int r0 = lane >> 3;           // row-within-4-group
        const int c0 = lane & 7;            // 16B chunk
        const char* hf = (const char*)g_hfeats;
        char* fs = (char*)S.f;
        #pragma unroll
        for (int it = 0; it < 8; ++it) {
            const int r = it * 4 + r0;
            const int n = S.ib[r];
            const u32 dst = smem_u32(fs + r * 128 + ((c0 ^ (r & 7)) << 4));
            const char* src = hf + (size_t)n * 128 + c0 * 16;
            asm volatile("cp.async.cg.shared.global [%0], [%1], 16;"
                         :: "r"(dst), "l"(src));
        }
        asm volatile("cp.async.commit_group;" ::: "memory");
    }

    // ---------------- Phase 2b: A-frags while copies fly, then B + mma ----------
    const int q  = lane >> 3;
    const int rr = lane & 7;
    const u32 wtb = smem_u32(S.wt);
    const u32 fb  = smem_u32(S.f);

    // A: matrix q -> rows ((q&2)?8+rr:rr), k-chunk (q&1); row stride 48B
    const int lrA = ((q & 2) ? 8 : 0) + rr;
    const u32 addrA0 = wtb + (u32)(lrA * 48 + (q & 1) * 16);
    // B: matrix q -> rows ((q&1)?8+rr:rr), chunk base (q>>1); swizzled by rr
    const int lrB = ((q & 1) ? 8 : 0) + rr;
    const int chB = q >> 1;

    u32 a[2][4];
    #pragma unroll
    for (int kt = 0; kt < 2; ++kt)
        LDSM_X4_TRANS(a[kt][0], a[kt][1], a[kt][2], a[kt][3],
                      addrA0 + kt * (16 * 48));

    float c[8][4];
    #pragma unroll
    for (int t = 0; t < 8; ++t)
        #pragma unroll
        for (int j = 0; j < 4; ++j) c[t][j] = 0.0f;

    asm volatile("cp.async.wait_group 0;" ::: "memory");
    __syncwarp();   // cross-lane visibility of the async-filled F tile

    #pragma unroll
    for (int kt = 0; kt < 2; ++kt) {
        const u32 rowB = fb + (u32)((lrB + kt * 16) * 128);
        #pragma unroll
        for (int tp = 0; tp < 4; ++tp) {
            const int ch = chB + tp * 2;
            u32 b0, b1, b2, b3;
            LDSM_X4_TRANS(b0, b1, b2, b3, rowB + (u32)((ch ^ rr) << 4));
            MMA16816(c[2 * tp],     a[kt][0], a[kt][1], a[kt][2], a[kt][3], b0, b1);
            MMA16816(c[2 * tp + 1], a[kt][0], a[kt][1], a[kt][2], a[kt][3], b2, b3);
        }
    }

    // ---------------- Epilogue: store c-frags (mean already applied) -----------
    const int gg = lane >> 2;
    const int tg = lane & 3;
    float* orow = out + (size_t)v * 576;

    #pragma unroll
    for (int t = 0; t < 8; ++t)
        *(float2*)(orow + gg * 64 + t * 8 + tg * 2) = make_float2(c[t][0], c[t][1]);

    if (gg == 0) {
        #pragma unroll
        for (int t = 0; t < 8; ++t)
            *(float2*)(orow + 8 * 64 + t * 8 + tg * 2) = make_float2(c[t][2], c[t][3]);
    }
}

extern "C" void kernel_launch(void* const* d_in, const int* in_sizes, int n_in,
                              void* d_out, int out_size)
{
    const float* coords = (const float*)d_in[0];
    const float* feats  = (const float*)d_in[1];
    const int*   nbr    = (const int*)  d_in[3];
    const float* ls     = (const float*)d_in[4];
    float* out = (float*)d_out;

    const int V = in_sizes[0] / 4;

    // pre-pass: fp32 -> fp16 feature table
    const int n8 = V * 8;
    cvt_kernel<<<(n8 + 255) / 256, 256>>>(feats, n8);

    const int blocks = (V + 3) / 4;   // one vertex per warp, 4 warps/block
    spcnn_kernel<<<blocks, 128>>>(coords, nbr, ls, out, V);
}

// round 15
// speedup vs baseline: 2.1600x; 1.0825x over previous
#include <cuda_runtime.h>
#include <cuda_fp16.h>
#include <cstdint>

// SoftPixelCNN R15: R14 (tensor-core GEMM + swizzled SMEM + cp.async.cg
// gather) with an SMEM-staged epilogue.
// The mma C-fragment confines output row o to 4 lanes, so direct stores
// touch 8 lines per STG (72 wf/vertex). Stage C into warp-private SMEM
// (overlaid on the dead wt/f tiles) in a bank-optimal layout, then store
// contiguous float4 rounds (4 lines per STG): 72 -> ~60 wf per vertex.

typedef unsigned u32;

#define MAXV 50176
__device__ __align__(16) uint4 g_hfeats[MAXV * 8];   // V x 64 fp16 (128 B rows)

__device__ __forceinline__ u32 pack_h2(float a, float b) {
    const __half2 h = __floats2half2_rn(a, b);
    return *(const u32*)&h;
}

__global__ __launch_bounds__(256)
void cvt_kernel(const float* __restrict__ feats, int n8)  // n8 = V*8
{
    const int i = blockIdx.x * blockDim.x + threadIdx.x;
    if (i >= n8) return;
    const float4 a = ((const float4*)feats)[2 * i];
    const float4 b = ((const float4*)feats)[2 * i + 1];
    uint4 r;
    r.x = pack_h2(a.x, a.y);
    r.y = pack_h2(a.z, a.w);
    r.z = pack_h2(b.x, b.y);
    r.w = pack_h2(b.z, b.w);
    g_hfeats[i] = r;
}

__device__ __forceinline__ u32 smem_u32(const void* p) {
    return (u32)__cvta_generic_to_shared(p);
}

#define LDSM_X4_TRANS(x0, x1, x2, x3, addr)                                   \
    asm volatile("ldmatrix.sync.aligned.m8n8.x4.trans.shared.b16 "            \
                 "{%0,%1,%2,%3}, [%4];"                                        \
                 : "=r"(x0), "=r"(x1), "=r"(x2), "=r"(x3) : "r"(addr))

#define MMA16816(c, a0, a1, a2, a3, b0, b1)                                   \
    asm volatile("mma.sync.aligned.m16n8k16.row.col.f32.f16.f16.f32 "         \
                 "{%0,%1,%2,%3}, {%4,%5,%6,%7}, {%8,%9}, {%0,%1,%2,%3};"       \
                 : "+f"((c)[0]), "+f"((c)[1]), "+f"((c)[2]), "+f"((c)[3])      \
                 : "r"(a0), "r"(a1), "r"(a2), "r"(a3), "r"(b0), "r"(b1))

__global__ __launch_bounds__(128, 8)
void spcnn_kernel(const float* __restrict__ coords,   // (V,4)
                  const int*   __restrict__ nbr,      // (V,32)
                  const float* __restrict__ ls,       // (1,)
                  float*       __restrict__ out,      // (V,576)
                  int V)
{
    const int warp = threadIdx.x >> 5;
    const int lane = threadIdx.x & 31;
    const int v    = blockIdx.x * 4 + warp;

    union WS {
        struct {
            __half wt[32][24];   // 1536 B: W^T rows padded to 48B
            __half f [32][64];   // 4096 B: gathered rows, chunk-XOR swizzled
            int    ib[32];       // 128 B : neighbor indices
        } p;
        float stage[720];        // 2880 B: epilogue staging (overlaid)
    };
    __shared__ __align__(16) WS ws[4];
    WS& S = ws[warp];

    if (v >= V) return;
    const float g = 10.0f * ls[0];

    // ---------------- Phase 1: lane k -> W^T row k (fp16, mean-folded) ---------
    {
        const int idx = nbr[v * 32 + lane];
        const float4 cv = ((const float4*)coords)[v];
        const float4 cn = ((const float4*)coords)[idx];
        const float dx = cv.x - cn.x;
        const float dy = cv.y - cn.y;
        const float dz = cv.z - cn.z;
        const float dw = cv.w - cn.w;
        const float base = dx*dx + dy*dy + dz*dz + dw*dw;
        const float b1 = base + 1.0f;

        // OFFSETS (verified R1): o0=0 o1=-y o2=-x o3=-z o4=-w o5=+w o6=+z o7=+x o8=+y
        const float s = 0.03125f;   // 1/K folded into W
        const float w0 = s * __expf(-g * base);
        const float w1 = s * __expf(-g * (b1 - 2.0f * dy));
        const float w2 = s * __expf(-g * (b1 - 2.0f * dx));
        const float w3 = s * __expf(-g * (b1 - 2.0f * dz));
        const float w4 = s * __expf(-g * (b1 - 2.0f * dw));
        const float w5 = s * __expf(-g * (b1 + 2.0f * dw));
        const float w6 = s * __expf(-g * (b1 + 2.0f * dz));
        const float w7 = s * __expf(-g * (b1 + 2.0f * dx));
        const float w8 = s * __expf(-g * (b1 + 2.0f * dy));

        uint4 lo, hi;
        lo.x = pack_h2(w0, w1);
        lo.y = pack_h2(w2, w3);
        lo.z = pack_h2(w4, w5);
        lo.w = pack_h2(w6, w7);
        hi.x = pack_h2(w8, 0.0f);
        hi.y = 0u; hi.z = 0u; hi.w = 0u;
        *(uint4*)&S.p.wt[lane][0] = lo;    // bytes 0-15  (k-chunk 0)
        *(uint4*)&S.p.wt[lane][8] = hi;    // bytes 16-31 (k-chunk 1)
        S.p.ib[lane] = idx;
    }
    __syncwarp();

    // ---------------- Phase 2a: async gather straight into swizzled SMEM --------
    {
        const int r0 = lane >> 3;           // row-within-4-group
        const int c0 = lane & 7;            // 16B chunk
        const char* hf = (const char*)g_hfeats;
        char* fs = (char*)S.p.f;
        #pragma unroll
        for (int it = 0; it < 8; ++it) {
            const int r = it * 4 + r0;
            const int n = S.p.ib[r];
            const u32 dst = smem_u32(fs + r * 128 + ((c0 ^ (r & 7)) << 4));
            const char* src = hf + (size_t)n * 128 + c0 * 16;
            asm volatile("cp.async.cg.shared.global [%0], [%1], 16;"
                         :: "r"(dst), "l"(src));
        }
        asm volatile("cp.async.commit_group;" ::: "memory");
    }

    // ---------------- Phase 2b: A-frags while copies fly, then B + mma ----------
    const int q  = lane >> 3;
    const int rr = lane & 7;
    const u32 wtb = smem_u32(S.p.wt);
    const u32 fb  = smem_u32(S.p.f);

    const int lrA = ((q & 2) ? 8 : 0) + rr;
    const u32 addrA0 = wtb + (u32)(lrA * 48 + (q & 1) * 16);
    const int lrB = ((q & 1) ? 8 : 0) + rr;
    const int chB = q >> 1;

    u32 a[2][4];
    #pragma unroll
    for (int kt = 0; kt < 2; ++kt)
        LDSM_X4_TRANS(a[kt][0], a[kt][1], a[kt][2], a[kt][3],
                      addrA0 + kt * (16 * 48));

    float c[8][4];
    #pragma unroll
    for (int t = 0; t < 8; ++t)
        #pragma unroll
        for (int j = 0; j < 4; ++j) c[t][j] = 0.0f;

    asm volatile("cp.async.wait_group 0;" ::: "memory");
    __syncwarp();   // cross-lane visibility of the async-filled F tile

    #pragma unroll
    for (int kt = 0; kt < 2; ++kt) {
        const u32 rowB = fb + (u32)((lrB + kt * 16) * 128);
        #pragma unroll
        for (int tp = 0; tp < 4; ++tp) {
            const int ch = chB + tp * 2;
            u32 b0, b1, b2, b3;
            LDSM_X4_TRANS(b0, b1, b2, b3, rowB + (u32)((ch ^ rr) << 4));
            MMA16816(c[2 * tp],     a[kt][0], a[kt][1], a[kt][2], a[kt][3], b0, b1);
            MMA16816(c[2 * tp + 1], a[kt][0], a[kt][1], a[kt][2], a[kt][3], b2, b3);
        }
    }

    // ---------------- Epilogue: SMEM-staged transpose, contiguous stores --------
    // stage word map: D[o][f] (o<8) at 72*t + 2*(4o+tg) + p  where f=8t+2tg+p
    //                 D[8][f]        at 648 + 8t + 2tg + p
    __syncwarp();   // all ldmatrix reads of wt/f done before overlay write
    float* stg = S.stage;

    #pragma unroll
    for (int t = 0; t < 8; ++t)
        *(float2*)&stg[72 * t + 2 * lane] = make_float2(c[t][0], c[t][1]);
    if (lane < 4) {
        #pragma unroll
        for (int t = 0; t < 8; ++t)
            *(float2*)&stg[648 + 8 * t + 2 * lane] = make_float2(c[t][2], c[t][3]);
    }
    __syncwarp();

    float* orow = out + (size_t)v * 576;
    const int tl = (lane & 15) >> 1;     // t for this lane's output chunk
    const int sl = 4 * (lane & 1);       // 2*tg (tg in {0,2})
    const int ol = lane >> 4;            // o parity

    #pragma unroll
    for (int r = 0; r < 4; ++r) {
        const int o = 2 * r + ol;
        const float4 d = *(const float4*)&stg[72 * tl + 8 * o + sl];
        *(float4*)(orow + 128 * r + 4 * lane) = d;
    }
    if (lane < 16) {
        const float4 d = *(const float4*)&stg[648 + 8 * (lane >> 1) + 4 * (lane & 1)];
        *(float4*)(orow + 512 + 4 * lane) = d;
    }
}

extern "C" void kernel_launch(void* const* d_in, const int* in_sizes, int n_in,
                              void* d_out, int out_size)
{
    const float* coords = (const float*)d_in[0];
    const float* feats  = (const float*)d_in[1];
    const int*   nbr    = (const int*)  d_in[3];
    const float* ls     = (const float*)d_in[4];
    float* out = (float*)d_out;

    const int V = in_sizes[0] / 4;

    // pre-pass: fp32 -> fp16 feature table
    const int n8 = V * 8;
    cvt_kernel<<<(n8 + 255) / 256, 256>>>(feats, n8);

    const int blocks = (V + 3) / 4;   // one vertex per warp, 4 warps/block
    spcnn_kernel<<<blocks, 128>>>(coords, nbr, ls, out, V);
}

// round 16
// speedup vs baseline: 2.3478x; 1.0870x over previous
#include <cuda_runtime.h>
#include <cuda_fp16.h>
#include <cstdint>

// SoftPixelCNN R16: R15 with the two L2 gather latencies overlapped.
// The F-tile cp.async needs only neighbor indices, so it is issued FIRST
// (indices broadcast via shfl, eliminating the ib[] SMEM staging), and the
// entire phase-1 (coord gather + exp + W^T STS) executes while the F tile
// is in flight. ldmatrix A also runs before the cp.async wait.
// Everything else identical to R15 (swizzled tiles, staged epilogue).

typedef unsigned u32;

#define MAXV 50176
__device__ __align__(16) uint4 g_hfeats[MAXV * 8];   // V x 64 fp16 (128 B rows)

__device__ __forceinline__ u32 pack_h2(float a, float b) {
    const __half2 h = __floats2half2_rn(a, b);
    return *(const u32*)&h;
}

__global__ __launch_bounds__(256)
void cvt_kernel(const float* __restrict__ feats, int n8)  // n8 = V*8
{
    const int i = blockIdx.x * blockDim.x + threadIdx.x;
    if (i >= n8) return;
    const float4 a = ((const float4*)feats)[2 * i];
    const float4 b = ((const float4*)feats)[2 * i + 1];
    uint4 r;
    r.x = pack_h2(a.x, a.y);
    r.y = pack_h2(a.z, a.w);
    r.z = pack_h2(b.x, b.y);
    r.w = pack_h2(b.z, b.w);
    g_hfeats[i] = r;
}

__device__ __forceinline__ u32 smem_u32(const void* p) {
    return (u32)__cvta_generic_to_shared(p);
}

#define LDSM_X4_TRANS(x0, x1, x2, x3, addr)                                   \
    asm volatile("ldmatrix.sync.aligned.m8n8.x4.trans.shared.b16 "            \
                 "{%0,%1,%2,%3}, [%4];"                                        \
                 : "=r"(x0), "=r"(x1), "=r"(x2), "=r"(x3) : "r"(addr))

#define MMA16816(c, a0, a1, a2, a3, b0, b1)                                   \
    asm volatile("mma.sync.aligned.m16n8k16.row.col.f32.f16.f16.f32 "         \
                 "{%0,%1,%2,%3}, {%4,%5,%6,%7}, {%8,%9}, {%0,%1,%2,%3};"       \
                 : "+f"((c)[0]), "+f"((c)[1]), "+f"((c)[2]), "+f"((c)[3])      \
                 : "r"(a0), "r"(a1), "r"(a2), "r"(a3), "r"(b0), "r"(b1))

__global__ __launch_bounds__(128, 8)
void spcnn_kernel(const float* __restrict__ coords,   // (V,4)
                  const int*   __restrict__ nbr,      // (V,32)
                  const float* __restrict__ ls,       // (1,)
                  float*       __restrict__ out,      // (V,576)
                  int V)
{
    const int warp = threadIdx.x >> 5;
    const int lane = threadIdx.x & 31;
    const int v    = blockIdx.x * 4 + warp;

    union WS {
        struct {
            __half wt[32][24];   // 1536 B: W^T rows padded to 48B
            __half f [32][64];   // 4096 B: gathered rows, chunk-XOR swizzled
        } p;
        float stage[720];        // 2880 B: epilogue staging (overlaid)
    };
    __shared__ __align__(16) WS ws[4];
    WS& S = ws[warp];

    if (v >= V) return;
    const float g = 10.0f * ls[0];

    // ---------------- Step 1: indices -> F-tile cp.async FIRST ------------------
    const int idx = nbr[v * 32 + lane];    // lane = neighbor slot k

    {
        const int r0 = lane >> 3;           // row-within-4-group
        const int c0 = lane & 7;            // 16B chunk
        const char* hf = (const char*)g_hfeats;
        char* fs = (char*)S.p.f;
        #pragma unroll
        for (int it = 0; it < 8; ++it) {
            const int r = it * 4 + r0;
            const int n = __shfl_sync(0xFFFFFFFFu, idx, r);
            const u32 dst = smem_u32(fs + r * 128 + ((c0 ^ (r & 7)) << 4));
            const char* src = hf + (size_t)n * 128 + c0 * 16;
            asm volatile("cp.async.cg.shared.global [%0], [%1], 16;"
                         :: "r"(dst), "l"(src));
        }
        asm volatile("cp.async.commit_group;" ::: "memory");
    }

    // ---------------- Step 2: phase-1 under the F-gather latency ----------------
    {
        const float4 cv = ((const float4*)coords)[v];
        const float4 cn = ((const float4*)coords)[idx];
        const float dx = cv.x - cn.x;
        const float dy = cv.y - cn.y;
        const float dz = cv.z - cn.z;
        const float dw = cv.w - cn.w;
        const float base = dx*dx + dy*dy + dz*dz + dw*dw;
        const float b1 = base + 1.0f;

        // OFFSETS (verified R1): o0=0 o1=-y o2=-x o3=-z o4=-w o5=+w o6=+z o7=+x o8=+y
        const float s = 0.03125f;   // 1/K folded into W
        const float w0 = s * __expf(-g * base);
        const float w1 = s * __expf(-g * (b1 - 2.0f * dy));
        const float w2 = s * __expf(-g * (b1 - 2.0f * dx));
        const float w3 = s * __expf(-g * (b1 - 2.0f * dz));
        const float w4 = s * __expf(-g * (b1 - 2.0f * dw));
        const float w5 = s * __expf(-g * (b1 + 2.0f * dw));
        const float w6 = s * __expf(-g * (b1 + 2.0f * dz));
        const float w7 = s * __expf(-g * (b1 + 2.0f * dx));
        const float w8 = s * __expf(-g * (b1 + 2.0f * dy));

        uint4 lo, hi;
        lo.x = pack_h2(w0, w1);
        lo.y = pack_h2(w2, w3);
        lo.z = pack_h2(w4, w5);
        lo.w = pack_h2(w6, w7);
        hi.x = pack_h2(w8, 0.0f);
        hi.y = 0u; hi.z = 0u; hi.w = 0u;
        *(uint4*)&S.p.wt[lane][0] = lo;    // bytes 0-15  (k-chunk 0)
        *(uint4*)&S.p.wt[lane][8] = hi;    // bytes 16-31 (k-chunk 1)
    }
    __syncwarp();   // wt visible for ldmatrix A

    // ---------------- Step 3: A-frags, then wait for F, then B + mma ------------
    const int q  = lane >> 3;
    const int rr = lane & 7;
    const u32 wtb = smem_u32(S.p.wt);
    const u32 fb  = smem_u32(S.p.f);

    const int lrA = ((q & 2) ? 8 : 0) + rr;
    const u32 addrA0 = wtb + (u32)(lrA * 48 + (q & 1) * 16);
    const int lrB = ((q & 1) ? 8 : 0) + rr;
    const int chB = q >> 1;

    u32 a[2][4];
    #pragma unroll
    for (int kt = 0; kt < 2; ++kt)
        LDSM_X4_TRANS(a[kt][0], a[kt][1], a[kt][2], a[kt][3],
                      addrA0 + kt * (16 * 48));

    float c[8][4];
    #pragma unroll
    for (int t = 0; t < 8; ++t)
        #pragma unroll
        for (int j = 0; j < 4; ++j) c[t][j] = 0.0f;

    asm volatile("cp.async.wait_group 0;" ::: "memory");
    __syncwarp();   // cross-lane visibility of the async-filled F tile

    #pragma unroll
    for (int kt = 0; kt < 2; ++kt) {
        const u32 rowB = fb + (u32)((lrB + kt * 16) * 128);
        #pragma unroll
        for (int tp = 0; tp < 4; ++tp) {
            const int ch = chB + tp * 2;
            u32 b0, b1, b2, b3;
            LDSM_X4_TRANS(b0, b1, b2, b3, rowB + (u32)((ch ^ rr) << 4));
            MMA16816(c[2 * tp],     a[kt][0], a[kt][1], a[kt][2], a[kt][3], b0, b1);
            MMA16816(c[2 * tp + 1], a[kt][0], a[kt][1], a[kt][2], a[kt][3], b2, b3);
        }
    }

    // ---------------- Epilogue: SMEM-staged transpose, contiguous stores --------
    // stage word map: D[o][f] (o<8) at 72*t + 2*(4o+tg) + p  where f=8t+2tg+p
    //                 D[8][f]        at 648 + 8t + 2tg + p
    __syncwarp();   // all ldmatrix reads of wt/f done before overlay write
    float* stg = S.stage;

    #pragma unroll
    for (int t = 0; t < 8; ++t)
        *(float2*)&stg[72 * t + 2 * lane] = make_float2(c[t][0], c[t][1]);
    if (lane < 4) {
        #pragma unroll
        for (int t = 0; t < 8; ++t)
            *(float2*)&stg[648 + 8 * t + 2 * lane] = make_float2(c[t][2], c[t][3]);
    }
    __syncwarp();

    float* orow = out + (size_t)v * 576;
    const int tl = (lane & 15) >> 1;     // t for this lane's output chunk
    const int sl = 4 * (lane & 1);       // 2*tg (tg in {0,2})
    const int ol = lane >> 4;            // o parity

    #pragma unroll
    for (int r = 0; r < 4; ++r) {
        const int o = 2 * r + ol;
        const float4 d = *(const float4*)&stg[72 * tl + 8 * o + sl];
        *(float4*)(orow + 128 * r + 4 * lane) = d;
    }
    if (lane < 16) {
        const float4 d = *(const float4*)&stg[648 + 8 * (lane >> 1) + 4 * (lane & 1)];
        *(float4*)(orow + 512 + 4 * lane) = d;
    }
}

extern "C" void kernel_launch(void* const* d_in, const int* in_sizes, int n_in,
                              void* d_out, int out_size)
{
    const float* coords = (const float*)d_in[0];
    const float* feats  = (const float*)d_in[1];
    const int*   nbr    = (const int*)  d_in[3];
    const float* ls     = (const float*)d_in[4];
    float* out = (float*)d_out;

    const int V = in_sizes[0] / 4;

    // pre-pass: fp32 -> fp16 feature table
    const int n8 = V * 8;
    cvt_kernel<<<(n8 + 255) / 256, 256>>>(feats, n8);

    const int blocks = (V + 3) / 4;   // one vertex per warp, 4 warps/block
    spcnn_kernel<<<blocks, 128>>>(coords, nbr, ls, out, V);
}